// round 1
// baseline (speedup 1.0000x reference)
#include <cuda_runtime.h>
#include <cstdint>

#define NNODES 4096
#define NG     8
#define MPER   512
#define NW     16   // 512 bits = 16 uint32 words per row (block-local columns)

// Scratch (no allocation allowed -> device globals)
__device__ uint32_t g_mask[NNODES * NW];   // A bitmask, block-local columns
__device__ int      g_deg[NNODES];
__device__ float    g_feat[NNODES * 7];

// ---------------------------------------------------------------------------
// K1: pack block-diagonal strip of A into bitmask + degree. One warp per row.
// ---------------------------------------------------------------------------
__global__ void __launch_bounds__(256) pack_kernel(const float* __restrict__ A) {
    int warp = (blockIdx.x * blockDim.x + threadIdx.x) >> 5;
    int lane = threadIdx.x & 31;
    if (warp >= NNODES) return;
    int n  = warp;
    int g  = n >> 9;
    long base = (long)n * NNODES + ((long)g << 9);   // strip A[n, lo:lo+512]
    int deg = 0;
    #pragma unroll
    for (int w = 0; w < NW; w++) {
        float v = A[base + w * 32 + lane];
        unsigned word = __ballot_sync(0xffffffffu, v != 0.0f);
        if (lane == w) g_mask[n * NW + w] = word;
        deg += __popc(word);
    }
    if (lane == 0) g_deg[n] = deg;
}

// ---------------------------------------------------------------------------
// K2: per-row heavy pass. 16 blocks per graph, 256 threads (8 warps),
// warp handles 4 rows. Bitmask of the whole graph in smem.
// For row n: b_v = sum over k in ego1(n) of A[k,v] via broadcast smem loads;
// lane owns columns v = 32*j + lane, j = 0..15 (16 int counters in regs).
// ---------------------------------------------------------------------------
__global__ void __launch_bounds__(256) rowstats_kernel() {
    __shared__ uint32_t smask[MPER * NW];   // 32 KB
    __shared__ int      sdeg[MPER];

    int g   = blockIdx.x >> 4;
    int sub = blockIdx.x & 15;
    int lo  = g << 9;
    int t   = threadIdx.x;

    // load graph's bitmask + degrees into smem
    const uint4* src = reinterpret_cast<const uint4*>(&g_mask[lo * NW]);
    uint4*       dst = reinterpret_cast<uint4*>(smask);
    #pragma unroll
    for (int i = 0; i < 8; i++) dst[t + 256 * i] = src[t + 256 * i];
    sdeg[t]       = g_deg[lo + t];
    sdeg[t + 256] = g_deg[lo + t + 256];
    __syncthreads();

    int warp = t >> 5, lane = t & 31;

    for (int r = 0; r < 4; r++) {
        int nl = sub * 32 + warp * 4 + r;       // local row in [0,512)

        // m1 row = A row | diagonal bit (identical in all lanes; broadcast LDS)
        uint32_t m[NW];
        #pragma unroll
        for (int w = 0; w < NW; w++) m[w] = smask[nl * NW + w];
        m[nl >> 5] |= 1u << (nl & 31);

        int cnt[NW];
        #pragma unroll
        for (int j = 0; j < NW; j++) cnt[j] = 0;

        // accumulate b_v = sum_{k in ego1} A[k,v]
        #pragma unroll
        for (int w = 0; w < NW; w++) {
            uint32_t bits = m[w];
            while (bits) {
                int k = w * 32 + __ffs(bits) - 1;
                bits &= bits - 1;
                const uint4* r4 = reinterpret_cast<const uint4*>(&smask[k * NW]);
                #pragma unroll
                for (int q = 0; q < 4; q++) {
                    uint4 w4 = r4[q];   // broadcast: all lanes same address
                    cnt[q * 4 + 0] += (w4.x >> lane) & 1u;
                    cnt[q * 4 + 1] += (w4.y >> lane) & 1u;
                    cnt[q * 4 + 2] += (w4.z >> lane) & 1u;
                    cnt[q * 4 + 3] += (w4.w >> lane) & 1u;
                }
            }
        }

        // per-lane partial stats over its 16 columns
        int f4r = 0, m2cnt = 0, m2deg = 0, f2num = 0;
        #pragma unroll
        for (int j = 0; j < NW; j++) {
            int v     = j * 32 + lane;
            int m1bit = (m[j] >> lane) & 1;          // includes diagonal
            int abit  = (v == nl) ? 0 : m1bit;       // A bit (no self loop)
            f4r  += cnt[j] * m1bit;
            int m2 = (cnt[j] > 0) ? 1 : 0;           // M2 == (B>0) exactly (deg>=1)
            m2cnt += m2;
            int dv = sdeg[v];
            m2deg += m2 ? dv : 0;
            f2num += abit ? dv : 0;
        }

        // warp reduce the 4 integer sums
        #pragma unroll
        for (int o = 16; o; o >>= 1) {
            f4r   += __shfl_down_sync(0xffffffffu, f4r,   o);
            m2cnt += __shfl_down_sync(0xffffffffu, m2cnt, o);
            m2deg += __shfl_down_sync(0xffffffffu, m2deg, o);
            f2num += __shfl_down_sync(0xffffffffu, f2num, o);
        }

        if (lane == 0) {
            int   n   = lo + nl;
            float deg = (float)sdeg[nl];
            float f0  = deg;
            float f1v = 0.0f;
            if (deg > 1.0f) f1v = 2.0f * ((float)f4r - deg) / (deg * (deg - 1.0f));
            float f2v = (deg > 0.0f) ? (float)f2num / deg : 0.0f;
            float f4v = 0.5f * (float)f4r;
            float f5v = (float)m2deg - 2.0f * (float)f4r;
            float f6v = (float)m2cnt - deg - 1.0f;
            float* F = &g_feat[n * 7];
            F[0] = f0; F[1] = f1v; F[2] = f2v; F[4] = f4v; F[5] = f5v; F[6] = f6v;
        }
    }
}

// ---------------------------------------------------------------------------
// K3: f3 = mean of f1 over neighbors. One block per graph, thread per node.
// ---------------------------------------------------------------------------
__global__ void __launch_bounds__(512) f3_kernel() {
    __shared__ float f1s[MPER];
    int g = blockIdx.x, lo = g << 9, t = threadIdx.x;
    f1s[t] = g_feat[(lo + t) * 7 + 1];
    __syncthreads();
    int n = lo + t;
    float s = 0.0f;
    #pragma unroll
    for (int w = 0; w < NW; w++) {
        uint32_t bits = g_mask[n * NW + w];
        while (bits) {
            int v = w * 32 + __ffs(bits) - 1;
            bits &= bits - 1;
            s += f1s[v];
        }
    }
    float deg = (float)g_deg[n];
    g_feat[n * 7 + 3] = (deg > 0.0f) ? s / deg : 0.0f;
}

// ---------------------------------------------------------------------------
// K4: per-graph statistics. One block per graph, thread per node.
// ---------------------------------------------------------------------------
__device__ __forceinline__ float warp_sum(float v) {
    #pragma unroll
    for (int o = 16; o; o >>= 1) v += __shfl_down_sync(0xffffffffu, v, o);
    return v;
}

__global__ void __launch_bounds__(512) stats_kernel(float* __restrict__ out) {
    __shared__ float sh[MPER];
    __shared__ float ws[16];
    __shared__ float ws2[16], ws3[16], ws4[16];
    __shared__ float bc[4];

    int g = blockIdx.x, lo = g << 9, t = threadIdx.x;
    int warp = t >> 5, lane = t & 31;

    for (int f = 0; f < 7; f++) {
        float x = g_feat[(lo + t) * 7 + f];
        sh[t] = x;
        __syncthreads();

        // mean
        float s = warp_sum(x);
        if (lane == 0) ws[warp] = s;
        __syncthreads();
        if (warp == 0) {
            float v = (lane < 16) ? ws[lane] : 0.0f;
            #pragma unroll
            for (int o = 8; o; o >>= 1) v += __shfl_down_sync(0xffffffffu, v, o);
            if (lane == 0) bc[0] = v * (1.0f / MPER);
        }
        __syncthreads();
        float mean = bc[0];

        // central moments
        float c  = x - mean;
        float c2 = c * c, c3 = c2 * c, c4 = c2 * c2;
        float s2 = warp_sum(c2), s3 = warp_sum(c3), s4 = warp_sum(c4);
        if (lane == 0) { ws2[warp] = s2; ws3[warp] = s3; ws4[warp] = s4; }
        __syncthreads();
        if (warp == 0) {
            float v2 = (lane < 16) ? ws2[lane] : 0.0f;
            float v3 = (lane < 16) ? ws3[lane] : 0.0f;
            float v4 = (lane < 16) ? ws4[lane] : 0.0f;
            #pragma unroll
            for (int o = 8; o; o >>= 1) {
                v2 += __shfl_down_sync(0xffffffffu, v2, o);
                v3 += __shfl_down_sync(0xffffffffu, v3, o);
                v4 += __shfl_down_sync(0xffffffffu, v4, o);
            }
            if (lane == 0) {
                float m2 = v2 * (1.0f / MPER);
                float m3 = v3 * (1.0f / MPER);
                float m4 = v4 * (1.0f / MPER);
                float eps = 1e-4f;
                float sd   = sqrtf(m2);
                float skew = m3 / fmaxf(m2 * sd, eps);
                float kurt = m4 / fmaxf(m2 * m2, eps);
                out[g * 35 +  0 + f] = mean;
                out[g * 35 + 14 + f] = sd;
                out[g * 35 + 21 + f] = skew;
                out[g * 35 + 28 + f] = kurt;
            }
        }

        // lower median via rank counting: sorted index (MPER-1)/2 = 255
        int lt = 0, eq = 0;
        for (int i = 0; i < MPER; i++) {
            float y = sh[i];            // broadcast read
            lt += (y <  x) ? 1 : 0;
            eq += (y == x) ? 1 : 0;
        }
        if (lt <= 255 && 255 < lt + eq) out[g * 35 + 7 + f] = x;
        __syncthreads();  // before sh is overwritten by next feature
    }
}

// ---------------------------------------------------------------------------
extern "C" void kernel_launch(void* const* d_in, const int* in_sizes, int n_in,
                              void* d_out, int out_size) {
    const float* A = (const float*)d_in[0];
    float* out = (float*)d_out;
    pack_kernel<<<NNODES / 8, 256>>>(A);     // 8 warps/block -> 512 blocks
    rowstats_kernel<<<NG * 16, 256>>>();
    f3_kernel<<<NG, MPER>>>();
    stats_kernel<<<NG, MPER>>>(out);
}

// round 2
// speedup vs baseline: 2.9744x; 2.9744x over previous
#include <cuda_runtime.h>
#include <cstdint>

#define NNODES 4096
#define NG     8
#define MPER   512
#define NW     16   // 512 bits = 16 uint32 words per row (block-local columns)

// Scratch (no allocation allowed -> device globals)
__device__ uint32_t g_mask[NNODES * NW];   // A bitmask, block-local columns
__device__ int      g_deg[NNODES];
__device__ float    g_feat[7 * NNODES];    // feature-major [7][4096]

// ---------------------------------------------------------------------------
// K1: pack block-diagonal strip of A into bitmask + degree. One warp per row.
// ---------------------------------------------------------------------------
__global__ void __launch_bounds__(256) pack_kernel(const float* __restrict__ A) {
    int warp = (blockIdx.x * blockDim.x + threadIdx.x) >> 5;
    int lane = threadIdx.x & 31;
    if (warp >= NNODES) return;
    int n  = warp;
    int g  = n >> 9;
    long base = (long)n * NNODES + ((long)g << 9);   // strip A[n, lo:lo+512]
    int deg = 0;
    #pragma unroll
    for (int w = 0; w < NW; w++) {
        float v = A[base + w * 32 + lane];
        unsigned word = __ballot_sync(0xffffffffu, v != 0.0f);
        if (lane == w) g_mask[n * NW + w] = word;
        deg += __popc(word);
    }
    if (lane == 0) g_deg[n] = deg;
}

// ---------------------------------------------------------------------------
// K2: per-row heavy pass. 16 blocks per graph, 512 threads (16 warps),
// warp handles 2 rows. Bitmask of the whole graph in smem.
// For row n: b_v = sum over k in ego1(n) of A[k,v] via broadcast smem loads;
// lane owns columns v = 32*j + lane, j = 0..15 (16 int counters in regs).
// ---------------------------------------------------------------------------
__global__ void __launch_bounds__(512) rowstats_kernel() {
    __shared__ uint32_t smask[MPER * NW];   // 32 KB
    __shared__ int      sdeg[MPER];

    int g   = blockIdx.x >> 4;
    int sub = blockIdx.x & 15;
    int lo  = g << 9;
    int t   = threadIdx.x;

    // load graph's bitmask + degrees into smem (2048 uint4 over 512 threads)
    const uint4* src = reinterpret_cast<const uint4*>(&g_mask[lo * NW]);
    uint4*       dst = reinterpret_cast<uint4*>(smask);
    #pragma unroll
    for (int i = 0; i < 4; i++) dst[t + 512 * i] = src[t + 512 * i];
    sdeg[t] = g_deg[lo + t];
    __syncthreads();

    int warp = t >> 5, lane = t & 31;

    for (int r = 0; r < 2; r++) {
        int nl = sub * 32 + warp * 2 + r;       // local row in [0,512)

        // m1 row = A row | diagonal bit (identical in all lanes; broadcast LDS)
        uint32_t m[NW];
        #pragma unroll
        for (int w = 0; w < NW; w++) m[w] = smask[nl * NW + w];
        m[nl >> 5] |= 1u << (nl & 31);

        int cnt[NW];
        #pragma unroll
        for (int j = 0; j < NW; j++) cnt[j] = 0;

        // accumulate b_v = sum_{k in ego1} A[k,v]
        #pragma unroll
        for (int w = 0; w < NW; w++) {
            uint32_t bits = m[w];
            while (bits) {
                int k = w * 32 + __ffs(bits) - 1;
                bits &= bits - 1;
                const uint4* r4 = reinterpret_cast<const uint4*>(&smask[k * NW]);
                #pragma unroll
                for (int q = 0; q < 4; q++) {
                    uint4 w4 = r4[q];   // broadcast: all lanes same address
                    cnt[q * 4 + 0] += (w4.x >> lane) & 1u;
                    cnt[q * 4 + 1] += (w4.y >> lane) & 1u;
                    cnt[q * 4 + 2] += (w4.z >> lane) & 1u;
                    cnt[q * 4 + 3] += (w4.w >> lane) & 1u;
                }
            }
        }

        // per-lane partial stats over its 16 columns
        int f4r = 0, m2cnt = 0, m2deg = 0, f2num = 0;
        #pragma unroll
        for (int j = 0; j < NW; j++) {
            int v     = j * 32 + lane;
            int m1bit = (m[j] >> lane) & 1;          // includes diagonal
            int abit  = (v == nl) ? 0 : m1bit;       // A bit (no self loop)
            f4r  += cnt[j] * m1bit;
            int m2 = (cnt[j] > 0) ? 1 : 0;           // M2 == (B>0) exactly (deg>=1)
            m2cnt += m2;
            int dv = sdeg[v];
            m2deg += m2 ? dv : 0;
            f2num += abit ? dv : 0;
        }

        // warp reduce the 4 integer sums
        #pragma unroll
        for (int o = 16; o; o >>= 1) {
            f4r   += __shfl_down_sync(0xffffffffu, f4r,   o);
            m2cnt += __shfl_down_sync(0xffffffffu, m2cnt, o);
            m2deg += __shfl_down_sync(0xffffffffu, m2deg, o);
            f2num += __shfl_down_sync(0xffffffffu, f2num, o);
        }

        if (lane == 0) {
            int   n   = lo + nl;
            float deg = (float)sdeg[nl];
            float f1v = 0.0f;
            if (deg > 1.0f) f1v = 2.0f * ((float)f4r - deg) / (deg * (deg - 1.0f));
            float f2v = (deg > 0.0f) ? (float)f2num / deg : 0.0f;
            float f4v = 0.5f * (float)f4r;
            float f5v = (float)m2deg - 2.0f * (float)f4r;
            float f6v = (float)m2cnt - deg - 1.0f;
            g_feat[0 * NNODES + n] = deg;
            g_feat[1 * NNODES + n] = f1v;
            g_feat[2 * NNODES + n] = f2v;
            g_feat[4 * NNODES + n] = f4v;
            g_feat[5 * NNODES + n] = f5v;
            g_feat[6 * NNODES + n] = f6v;
        }
    }
}

// ---------------------------------------------------------------------------
// K3: f3 = mean of f1 over neighbors. One block per graph, thread per node.
// ---------------------------------------------------------------------------
__global__ void __launch_bounds__(512) f3_kernel() {
    __shared__ float f1s[MPER];
    int g = blockIdx.x, lo = g << 9, t = threadIdx.x;
    f1s[t] = g_feat[1 * NNODES + lo + t];
    __syncthreads();
    int n = lo + t;
    float s = 0.0f;
    #pragma unroll
    for (int w = 0; w < NW; w++) {
        uint32_t bits = g_mask[n * NW + w];
        while (bits) {
            int v = w * 32 + __ffs(bits) - 1;
            bits &= bits - 1;
            s += f1s[v];
        }
    }
    float deg = (float)g_deg[n];
    g_feat[3 * NNODES + n] = (deg > 0.0f) ? s / deg : 0.0f;
}

// ---------------------------------------------------------------------------
// K4: per-graph statistics. One block per (graph, feature) pair: 56 blocks.
// Mean/moments by block reduction; median via bitonic sort of 512 values.
// ---------------------------------------------------------------------------
__device__ __forceinline__ float warp_sum(float v) {
    #pragma unroll
    for (int o = 16; o; o >>= 1) v += __shfl_down_sync(0xffffffffu, v, o);
    return v;
}

__global__ void __launch_bounds__(512) stats_kernel(float* __restrict__ out) {
    __shared__ float sh[MPER];
    __shared__ float r1[16], r2[16], r3[16], r4[16];
    __shared__ float bc;

    int b = blockIdx.x;
    int f = b >> 3;          // 0..6
    int g = b & 7;           // 0..7
    int lo = g << 9;
    int t = threadIdx.x;
    int warp = t >> 5, lane = t & 31;

    float x = g_feat[f * NNODES + lo + t];   // coalesced
    sh[t] = x;

    // mean
    float s = warp_sum(x);
    if (lane == 0) r1[warp] = s;
    __syncthreads();
    if (warp == 0) {
        float v = (lane < 16) ? r1[lane] : 0.0f;
        #pragma unroll
        for (int o = 8; o; o >>= 1) v += __shfl_down_sync(0xffffffffu, v, o);
        if (lane == 0) bc = v * (1.0f / MPER);
    }
    __syncthreads();
    float mean = bc;

    // central moments
    float c  = x - mean;
    float c2 = c * c, c3 = c2 * c, c4 = c2 * c2;
    float s2 = warp_sum(c2), s3 = warp_sum(c3), s4 = warp_sum(c4);
    if (lane == 0) { r2[warp] = s2; r3[warp] = s3; r4[warp] = s4; }
    __syncthreads();
    if (warp == 0) {
        float v2 = (lane < 16) ? r2[lane] : 0.0f;
        float v3 = (lane < 16) ? r3[lane] : 0.0f;
        float v4 = (lane < 16) ? r4[lane] : 0.0f;
        #pragma unroll
        for (int o = 8; o; o >>= 1) {
            v2 += __shfl_down_sync(0xffffffffu, v2, o);
            v3 += __shfl_down_sync(0xffffffffu, v3, o);
            v4 += __shfl_down_sync(0xffffffffu, v4, o);
        }
        if (lane == 0) {
            float m2 = v2 * (1.0f / MPER);
            float m3 = v3 * (1.0f / MPER);
            float m4 = v4 * (1.0f / MPER);
            float eps = 1e-4f;
            float sd   = sqrtf(m2);
            float skew = m3 / fmaxf(m2 * sd, eps);
            float kurt = m4 / fmaxf(m2 * m2, eps);
            out[g * 35 +  0 + f] = mean;
            out[g * 35 + 14 + f] = sd;
            out[g * 35 + 21 + f] = skew;
            out[g * 35 + 28 + f] = kurt;
        }
    }

    // median: bitonic sort sh ascending, take index (MPER-1)/2 = 255
    #pragma unroll 1
    for (int k = 2; k <= MPER; k <<= 1) {
        #pragma unroll 1
        for (int j = k >> 1; j > 0; j >>= 1) {
            __syncthreads();
            int ixj = t ^ j;
            if (ixj > t) {
                float a = sh[t], b2 = sh[ixj];
                bool up = ((t & k) == 0);
                if ((a > b2) == up) { sh[t] = b2; sh[ixj] = a; }
            }
        }
    }
    __syncthreads();
    if (t == 0) out[g * 35 + 7 + f] = sh[(MPER - 1) / 2];
}

// ---------------------------------------------------------------------------
extern "C" void kernel_launch(void* const* d_in, const int* in_sizes, int n_in,
                              void* d_out, int out_size) {
    const float* A = (const float*)d_in[0];
    float* out = (float*)d_out;
    pack_kernel<<<NNODES / 8, 256>>>(A);     // 8 warps/block -> 512 blocks
    rowstats_kernel<<<NG * 16, 512>>>();
    f3_kernel<<<NG, MPER>>>();
    stats_kernel<<<NG * 7, MPER>>>(out);
}

// round 3
// speedup vs baseline: 4.3786x; 1.4721x over previous
#include <cuda_runtime.h>
#include <cstdint>

#define NNODES 4096
#define NG     8
#define MPER   512
#define NW     16   // 512 bits = 16 uint32 words per row (block-local columns)

// Scratch (no allocation allowed -> device globals)
__device__ uint32_t g_mask[NNODES * NW];   // A bitmask, block-local columns
__device__ int      g_deg[NNODES];
__device__ float    g_feat[7 * NNODES];    // feature-major [7][4096]

// ---------------------------------------------------------------------------
// K1: pack block-diagonal strip of A into bitmask + degree. One warp per row.
// ---------------------------------------------------------------------------
__global__ void __launch_bounds__(256) pack_kernel(const float* __restrict__ A) {
    int warp = (blockIdx.x * blockDim.x + threadIdx.x) >> 5;
    int lane = threadIdx.x & 31;
    if (warp >= NNODES) return;
    int n  = warp;
    int g  = n >> 9;
    long base = (long)n * NNODES + ((long)g << 9);   // strip A[n, lo:lo+512]
    int deg = 0;
    #pragma unroll
    for (int w = 0; w < NW; w++) {
        float v = A[base + w * 32 + lane];
        unsigned word = __ballot_sync(0xffffffffu, v != 0.0f);
        if (lane == w) g_mask[n * NW + w] = word;
        deg += __popc(word);
    }
    if (lane == 0) g_deg[n] = deg;
}

// ---------------------------------------------------------------------------
// K2: per-row pass via popcount/OR formulation (A symmetric):
//   f4_raw = sum_{k in ego1(n)} popc(Arow_k & m1_n)
//   M2row  = OR_{k in ego1(n)} Arow_k            (== (B>0), covers M1)
// Half-warp per row: lane l (0..15) owns mask word l. 16 blocks/graph,
// 512 threads = 16 warps = 32 rows per block.
// ---------------------------------------------------------------------------
__global__ void __launch_bounds__(512) rowstats_kernel() {
    __shared__ uint32_t smask[MPER * NW];   // 32 KB
    __shared__ int      sdeg[MPER];

    int g   = blockIdx.x >> 4;
    int sub = blockIdx.x & 15;
    int lo  = g << 9;
    int t   = threadIdx.x;

    // load graph's bitmask + degrees into smem (2048 uint4 over 512 threads)
    const uint4* src = reinterpret_cast<const uint4*>(&g_mask[lo * NW]);
    uint4*       dst = reinterpret_cast<uint4*>(smask);
    #pragma unroll
    for (int i = 0; i < 4; i++) dst[t + 512 * i] = src[t + 512 * i];
    sdeg[t] = g_deg[lo + t];
    __syncthreads();

    int warp = t >> 5, lane = t & 31;
    int half = lane >> 4;            // 0/1: which row of this warp
    int l    = lane & 15;            // owned word index
    int nl   = sub * 32 + warp * 2 + half;   // local row in [0,512)

    // m1 word (A row word | diagonal bit if it lands in this word)
    uint32_t mw = smask[nl * NW + l];
    uint32_t diagbit = (l == (nl >> 5)) ? (1u << (nl & 31)) : 0u;
    mw |= diagbit;

    uint32_t m2 = 0;
    int f4r = 0;

    #pragma unroll 1
    for (int w2 = 0; w2 < NW; w2++) {
        // broadcast word w2 of this half's m1 row (held by lane (half*16 + w2))
        uint32_t bits = __shfl_sync(0xffffffffu, mw, (lane & 16) | w2);
        while (bits) {
            int k = w2 * 32 + __ffs(bits) - 1;
            bits &= bits - 1;
            uint32_t rk = smask[k * NW + l];   // lanes 0..15 consecutive words
            m2 |= rk;
            f4r += __popc(rk & mw);
        }
    }

    // per-word tail stats
    int m2cnt = __popc(m2);
    uint32_t aw = mw & ~diagbit;        // pure A row word
    int m2deg = 0, f2num = 0;
    uint32_t bits = m2;                 // m2 superset of aw
    while (bits) {
        int b = __ffs(bits) - 1;
        bits &= bits - 1;
        int dv = sdeg[l * 32 + b];
        m2deg += dv;
        f2num += ((aw >> b) & 1) ? dv : 0;
    }

    // reduce the 4 sums within each half-warp (width 16)
    #pragma unroll
    for (int o = 8; o; o >>= 1) {
        f4r   += __shfl_down_sync(0xffffffffu, f4r,   o, 16);
        m2cnt += __shfl_down_sync(0xffffffffu, m2cnt, o, 16);
        m2deg += __shfl_down_sync(0xffffffffu, m2deg, o, 16);
        f2num += __shfl_down_sync(0xffffffffu, f2num, o, 16);
    }

    if (l == 0) {
        int   n   = lo + nl;
        float deg = (float)sdeg[nl];
        float f1v = 0.0f;
        if (deg > 1.0f) f1v = 2.0f * ((float)f4r - deg) / (deg * (deg - 1.0f));
        float f2v = (deg > 0.0f) ? (float)f2num / deg : 0.0f;
        float f4v = 0.5f * (float)f4r;
        float f5v = (float)m2deg - 2.0f * (float)f4r;
        float f6v = (float)m2cnt - deg - 1.0f;
        g_feat[0 * NNODES + n] = deg;
        g_feat[1 * NNODES + n] = f1v;
        g_feat[2 * NNODES + n] = f2v;
        g_feat[4 * NNODES + n] = f4v;
        g_feat[5 * NNODES + n] = f5v;
        g_feat[6 * NNODES + n] = f6v;
    }
}

// ---------------------------------------------------------------------------
// K3: per-graph statistics + fused f3. One block per (graph, feature): 56.
// f==3 blocks compute f3 (neighbor mean of f1) in-block. Median via hybrid
// bitonic: shuffles for j<=16, smem exchange only for the 10 cross-warp steps.
// ---------------------------------------------------------------------------
__device__ __forceinline__ float warp_sum(float v) {
    #pragma unroll
    for (int o = 16; o; o >>= 1) v += __shfl_down_sync(0xffffffffu, v, o);
    return v;
}

__global__ void __launch_bounds__(512) stats_kernel(float* __restrict__ out) {
    __shared__ float sh[MPER];
    __shared__ float r1[16], r2[16], r3[16], r4[16];
    __shared__ float bc;

    int b = blockIdx.x;
    int f = b >> 3;          // 0..6
    int g = b & 7;           // 0..7
    int lo = g << 9;
    int t = threadIdx.x;
    int warp = t >> 5, lane = t & 31;

    float x;
    if (f == 3) {
        // f3 = mean over neighbors of f1
        sh[t] = g_feat[1 * NNODES + lo + t];
        __syncthreads();
        int n = lo + t;
        float s = 0.0f;
        const uint4* rm = reinterpret_cast<const uint4*>(&g_mask[n * NW]);
        #pragma unroll
        for (int q = 0; q < 4; q++) {
            uint4 u = rm[q];
            uint32_t ws[4] = {u.x, u.y, u.z, u.w};
            #pragma unroll
            for (int j = 0; j < 4; j++) {
                uint32_t bits = ws[j];
                int base = (q * 4 + j) * 32;
                while (bits) {
                    int v = base + __ffs(bits) - 1;
                    bits &= bits - 1;
                    s += sh[v];
                }
            }
        }
        float deg = (float)g_deg[n];
        x = (deg > 0.0f) ? s / deg : 0.0f;
        __syncthreads();   // done reading sh before median reuses it
    } else {
        x = g_feat[f * NNODES + lo + t];   // coalesced
    }

    // mean
    float s = warp_sum(x);
    if (lane == 0) r1[warp] = s;
    __syncthreads();
    if (warp == 0) {
        float v = (lane < 16) ? r1[lane] : 0.0f;
        #pragma unroll
        for (int o = 8; o; o >>= 1) v += __shfl_down_sync(0xffffffffu, v, o);
        if (lane == 0) bc = v * (1.0f / MPER);
    }
    __syncthreads();
    float mean = bc;

    // central moments
    float c  = x - mean;
    float c2 = c * c, c3 = c2 * c, c4 = c2 * c2;
    float s2 = warp_sum(c2), s3 = warp_sum(c3), s4 = warp_sum(c4);
    if (lane == 0) { r2[warp] = s2; r3[warp] = s3; r4[warp] = s4; }
    __syncthreads();
    if (warp == 0) {
        float v2 = (lane < 16) ? r2[lane] : 0.0f;
        float v3 = (lane < 16) ? r3[lane] : 0.0f;
        float v4 = (lane < 16) ? r4[lane] : 0.0f;
        #pragma unroll
        for (int o = 8; o; o >>= 1) {
            v2 += __shfl_down_sync(0xffffffffu, v2, o);
            v3 += __shfl_down_sync(0xffffffffu, v3, o);
            v4 += __shfl_down_sync(0xffffffffu, v4, o);
        }
        if (lane == 0) {
            float m2 = v2 * (1.0f / MPER);
            float m3 = v3 * (1.0f / MPER);
            float m4 = v4 * (1.0f / MPER);
            float eps = 1e-4f;
            float sd   = sqrtf(m2);
            float skew = m3 / fmaxf(m2 * sd, eps);
            float kurt = m4 / fmaxf(m2 * m2, eps);
            out[g * 35 +  0 + f] = mean;
            out[g * 35 + 14 + f] = sd;
            out[g * 35 + 21 + f] = skew;
            out[g * 35 + 28 + f] = kurt;
        }
    }

    // ---- lower median: hybrid bitonic sort, thread t holds element t ----
    #pragma unroll 1
    for (int k = 2; k <= MPER; k <<= 1) {
        bool dirUp = ((t & k) == 0);
        // cross-warp steps via smem
        #pragma unroll 1
        for (int j = k >> 1; j >= 32; j >>= 1) {
            __syncthreads();
            sh[t] = x;
            __syncthreads();
            float other = sh[t ^ j];
            bool amLow = ((t & j) == 0);
            x = (dirUp == amLow) ? fminf(x, other) : fmaxf(x, other);
        }
        // intra-warp steps via shuffle
        int j0 = (k >> 1 < 16) ? (k >> 1) : 16;
        #pragma unroll 1
        for (int j = j0; j >= 1; j >>= 1) {
            float other = __shfl_xor_sync(0xffffffffu, x, j);
            bool amLow = ((t & j) == 0);
            x = (dirUp == amLow) ? fminf(x, other) : fmaxf(x, other);
        }
    }
    if (t == (MPER - 1) / 2) out[g * 35 + 7 + f] = x;
}

// ---------------------------------------------------------------------------
extern "C" void kernel_launch(void* const* d_in, const int* in_sizes, int n_in,
                              void* d_out, int out_size) {
    const float* A = (const float*)d_in[0];
    float* out = (float*)d_out;
    pack_kernel<<<NNODES / 8, 256>>>(A);     // 8 warps/block -> 512 blocks
    rowstats_kernel<<<NG * 16, 512>>>();
    stats_kernel<<<NG * 7, MPER>>>(out);
}

// round 5
// speedup vs baseline: 4.4321x; 1.0122x over previous
#include <cuda_runtime.h>
#include <cstdint>

#define NNODES 4096
#define NG     8
#define MPER   512
#define NW     16   // 512 bits = 16 uint32 words per row (block-local columns)

// Scratch (no allocation allowed -> device globals)
__device__ uint32_t g_mask[NNODES * NW];   // A bitmask, block-local columns
__device__ int      g_deg[NNODES];
__device__ float    g_feat[7 * NNODES];    // feature-major [7][4096]

// ---------------------------------------------------------------------------
// K1: pack block-diagonal strip of A into bitmask + degree.
// One warp per 2 rows; float4 loads (8 LDG.128 in flight per thread);
// bits assembled locally as nibbles, combined via 3 shfl_down steps per chunk.
// ---------------------------------------------------------------------------
__global__ void __launch_bounds__(256) pack_kernel(const float* __restrict__ A) {
    int wid  = (blockIdx.x * blockDim.x + threadIdx.x) >> 5;   // 0..2047
    int lane = threadIdx.x & 31;
    int n0 = wid * 2;                      // even -> n0, n0+1 in same graph
    int g  = n0 >> 9;
    long base0 = (long)n0 * NNODES + ((long)g << 9);
    long base1 = base0 + NNODES;

    float4 a[2][4];
    #pragma unroll
    for (int c = 0; c < 4; c++) {
        a[0][c] = *reinterpret_cast<const float4*>(A + base0 + c * 128 + 4 * lane);
        a[1][c] = *reinterpret_cast<const float4*>(A + base1 + c * 128 + 4 * lane);
    }

    #pragma unroll
    for (int r = 0; r < 2; r++) {
        int n = n0 + r;
        int deg = 0;
        #pragma unroll
        for (int c = 0; c < 4; c++) {
            float4 v = a[r][c];
            uint32_t nib = (uint32_t)(v.x != 0.0f)
                         | ((uint32_t)(v.y != 0.0f) << 1)
                         | ((uint32_t)(v.z != 0.0f) << 2)
                         | ((uint32_t)(v.w != 0.0f) << 3);
            deg += __popc(nib);
            uint32_t w = nib;
            w |= __shfl_down_sync(0xffffffffu, w, 1, 8) << 4;
            w |= __shfl_down_sync(0xffffffffu, w, 2, 8) << 8;
            w |= __shfl_down_sync(0xffffffffu, w, 4, 8) << 16;
            if ((lane & 7) == 0)
                g_mask[n * NW + c * 4 + (lane >> 3)] = w;
        }
        #pragma unroll
        for (int o = 16; o; o >>= 1) deg += __shfl_down_sync(0xffffffffu, deg, o);
        if (lane == 0) g_deg[n] = deg;
    }
}

// ---------------------------------------------------------------------------
// K2: per-row pass via popcount/OR formulation (A symmetric):
//   f4_raw = sum_{k in ego1(n)} popc(Arow_k & m1_n)
//   M2row  = OR_{k in ego1(n)} Arow_k            (== (B>0), covers M1)
// Half-warp per row: lane l (0..15) owns mask word l. 16 blocks/graph,
// 512 threads = 16 warps = 32 rows per block. m2deg tail uses dp4a against
// byte-packed degrees (M2 is dense); f2num keeps a bit-loop (A row sparse).
// ---------------------------------------------------------------------------
__global__ void __launch_bounds__(512) rowstats_kernel() {
    __shared__ uint32_t smask[MPER * NW];   // 32 KB
    __shared__ int      sdeg[MPER];
    __shared__ uint32_t sdegp[MPER / 4];    // degrees packed as bytes

    int g   = blockIdx.x >> 4;
    int sub = blockIdx.x & 15;
    int lo  = g << 9;
    int t   = threadIdx.x;

    const uint4* src = reinterpret_cast<const uint4*>(&g_mask[lo * NW]);
    uint4*       dst = reinterpret_cast<uint4*>(smask);
    #pragma unroll
    for (int i = 0; i < 4; i++) dst[t + 512 * i] = src[t + 512 * i];
    sdeg[t] = g_deg[lo + t];
    __syncthreads();
    if (t < 128) {
        sdegp[t] = (uint32_t)sdeg[4 * t]
                 | ((uint32_t)sdeg[4 * t + 1] << 8)
                 | ((uint32_t)sdeg[4 * t + 2] << 16)
                 | ((uint32_t)sdeg[4 * t + 3] << 24);
    }
    __syncthreads();

    int warp = t >> 5, lane = t & 31;
    int half = lane >> 4;            // 0/1: which row of this warp
    int l    = lane & 15;            // owned word index
    int nl   = sub * 32 + warp * 2 + half;   // local row in [0,512)

    uint32_t mw = smask[nl * NW + l];
    uint32_t diagbit = (l == (nl >> 5)) ? (1u << (nl & 31)) : 0u;
    mw |= diagbit;

    uint32_t m2 = 0;
    int f4r = 0;

    #pragma unroll 1
    for (int w2 = 0; w2 < NW; w2++) {
        uint32_t bits = __shfl_sync(0xffffffffu, mw, (lane & 16) | w2);
        while (bits) {
            int k = w2 * 32 + __ffs(bits) - 1;
            bits &= bits - 1;
            uint32_t rk = smask[k * NW + l];
            m2 |= rk;
            f4r += __popc(rk & mw);
        }
    }

    // tail stats
    int m2cnt = __popc(m2);
    uint32_t aw = mw & ~diagbit;
    int f2num = 0;
    {
        uint32_t bits = aw;
        while (bits) {
            int b = __ffs(bits) - 1;
            bits &= bits - 1;
            f2num += sdeg[l * 32 + b];
        }
    }
    int m2deg;
    {
        const uint4* sp4 = reinterpret_cast<const uint4*>(sdegp);
        uint4 q0 = sp4[l * 2], q1 = sp4[l * 2 + 1];
        uint32_t dq[8] = {q0.x, q0.y, q0.z, q0.w, q1.x, q1.y, q1.z, q1.w};
        unsigned acc = 0u;
        #pragma unroll
        for (int j = 0; j < 8; j++) {
            uint32_t spread = (((m2 >> (4 * j)) & 0xFu) * 0x00204081u) & 0x01010101u;
            acc = __dp4a(spread, dq[j], acc);
        }
        m2deg = (int)acc;
    }

    #pragma unroll
    for (int o = 8; o; o >>= 1) {
        f4r   += __shfl_down_sync(0xffffffffu, f4r,   o, 16);
        m2cnt += __shfl_down_sync(0xffffffffu, m2cnt, o, 16);
        m2deg += __shfl_down_sync(0xffffffffu, m2deg, o, 16);
        f2num += __shfl_down_sync(0xffffffffu, f2num, o, 16);
    }

    if (l == 0) {
        int   n   = lo + nl;
        float deg = (float)sdeg[nl];
        float f1v = 0.0f;
        if (deg > 1.0f) f1v = 2.0f * ((float)f4r - deg) / (deg * (deg - 1.0f));
        float f2v = (deg > 0.0f) ? (float)f2num / deg : 0.0f;
        float f4v = 0.5f * (float)f4r;
        float f5v = (float)m2deg - 2.0f * (float)f4r;
        float f6v = (float)m2cnt - deg - 1.0f;
        g_feat[0 * NNODES + n] = deg;
        g_feat[1 * NNODES + n] = f1v;
        g_feat[2 * NNODES + n] = f2v;
        g_feat[4 * NNODES + n] = f4v;
        g_feat[5 * NNODES + n] = f5v;
        g_feat[6 * NNODES + n] = f6v;
    }
}

// ---------------------------------------------------------------------------
// K3: per-graph statistics + fused f3. One block per (graph, feature): 56.
// ---------------------------------------------------------------------------
__device__ __forceinline__ float warp_sum(float v) {
    #pragma unroll
    for (int o = 16; o; o >>= 1) v += __shfl_down_sync(0xffffffffu, v, o);
    return v;
}

__global__ void __launch_bounds__(512) stats_kernel(float* __restrict__ out) {
    __shared__ float sh[MPER];
    __shared__ float r1[16], r2[16], r3[16], r4[16];
    __shared__ float bc;

    int b = blockIdx.x;
    int f = b >> 3;          // 0..6
    int g = b & 7;           // 0..7
    int lo = g << 9;
    int t = threadIdx.x;
    int warp = t >> 5, lane = t & 31;

    float x;
    if (f == 3) {
        // f3 = mean over neighbors of f1
        sh[t] = g_feat[1 * NNODES + lo + t];
        __syncthreads();
        int n = lo + t;
        float s = 0.0f;
        const uint4* rm = reinterpret_cast<const uint4*>(&g_mask[n * NW]);
        #pragma unroll
        for (int q = 0; q < 4; q++) {
            uint4 u = rm[q];
            uint32_t ws[4] = {u.x, u.y, u.z, u.w};
            #pragma unroll
            for (int j = 0; j < 4; j++) {
                uint32_t bits = ws[j];
                int base = (q * 4 + j) * 32;
                while (bits) {
                    int v = base + __ffs(bits) - 1;
                    bits &= bits - 1;
                    s += sh[v];
                }
            }
        }
        float deg = (float)g_deg[n];
        x = (deg > 0.0f) ? s / deg : 0.0f;
        __syncthreads();   // done reading sh before median reuses it
    } else {
        x = g_feat[f * NNODES + lo + t];   // coalesced
    }

    // mean
    float s = warp_sum(x);
    if (lane == 0) r1[warp] = s;
    __syncthreads();
    if (warp == 0) {
        float v = (lane < 16) ? r1[lane] : 0.0f;
        #pragma unroll
        for (int o = 8; o; o >>= 1) v += __shfl_down_sync(0xffffffffu, v, o);
        if (lane == 0) bc = v * (1.0f / MPER);
    }
    __syncthreads();
    float mean = bc;

    // central moments
    float c  = x - mean;
    float c2 = c * c, c3 = c2 * c, c4 = c2 * c2;
    float s2 = warp_sum(c2), s3 = warp_sum(c3), s4 = warp_sum(c4);
    if (lane == 0) { r2[warp] = s2; r3[warp] = s3; r4[warp] = s4; }
    __syncthreads();
    if (warp == 0) {
        float v2 = (lane < 16) ? r2[lane] : 0.0f;
        float v3 = (lane < 16) ? r3[lane] : 0.0f;
        float v4 = (lane < 16) ? r4[lane] : 0.0f;
        #pragma unroll
        for (int o = 8; o; o >>= 1) {
            v2 += __shfl_down_sync(0xffffffffu, v2, o);
            v3 += __shfl_down_sync(0xffffffffu, v3, o);
            v4 += __shfl_down_sync(0xffffffffu, v4, o);
        }
        if (lane == 0) {
            float m2 = v2 * (1.0f / MPER);
            float m3 = v3 * (1.0f / MPER);
            float m4 = v4 * (1.0f / MPER);
            float eps = 1e-4f;
            float sd   = sqrtf(m2);
            float skew = m3 / fmaxf(m2 * sd, eps);
            float kurt = m4 / fmaxf(m2 * m2, eps);
            out[g * 35 +  0 + f] = mean;
            out[g * 35 + 14 + f] = sd;
            out[g * 35 + 21 + f] = skew;
            out[g * 35 + 28 + f] = kurt;
        }
    }

    // ---- lower median: hybrid bitonic sort, thread t holds element t ----
    #pragma unroll 1
    for (int k = 2; k <= MPER; k <<= 1) {
        bool dirUp = ((t & k) == 0);
        #pragma unroll 1
        for (int j = k >> 1; j >= 32; j >>= 1) {
            __syncthreads();
            sh[t] = x;
            __syncthreads();
            float other = sh[t ^ j];
            bool amLow = ((t & j) == 0);
            x = (dirUp == amLow) ? fminf(x, other) : fmaxf(x, other);
        }
        int j0 = (k >> 1 < 16) ? (k >> 1) : 16;
        #pragma unroll 1
        for (int j = j0; j >= 1; j >>= 1) {
            float other = __shfl_xor_sync(0xffffffffu, x, j);
            bool amLow = ((t & j) == 0);
            x = (dirUp == amLow) ? fminf(x, other) : fmaxf(x, other);
        }
    }
    if (t == (MPER - 1) / 2) out[g * 35 + 7 + f] = x;
}

// ---------------------------------------------------------------------------
extern "C" void kernel_launch(void* const* d_in, const int* in_sizes, int n_in,
                              void* d_out, int out_size) {
    const float* A = (const float*)d_in[0];
    float* out = (float*)d_out;
    pack_kernel<<<256, 256>>>(A);            // 8 warps/block, 2 rows/warp
    rowstats_kernel<<<NG * 16, 512>>>();
    stats_kernel<<<NG * 7, MPER>>>(out);
}